// round 7
// baseline (speedup 1.0000x reference)
#include <cuda_runtime.h>
#include <cuda_fp16.h>
#include <cstdint>

#define NN 4096
#define DD 64
#define NITER 50
#define REGI 10.0f
#define INV_REG 0.1f
#define EPSF 1e-16f
#define AB (1.0f / 4096.0f)
#define INV_SCALE (1.0f / 262144.0f)   // 2^-18
#define LN_SCALE 12.476649250079f      // 18*ln2
#define NBLK 128
#define NTHR 1024
#define DSM_BYTES 66560

// ---------------- persistent device state (no cudaMalloc allowed) ----------
__device__ uint4 g_E4[(size_t)NN * NN / 8];    // E*2^18 fp16 row-major, 32 MiB
__device__ uint4 g_ET4[(size_t)NN * NN / 8];   // transpose, 32 MiB
__device__ float g_xT[DD * NN];
__device__ float g_yT[DD * NN];
__device__ __align__(16) float g_xs[NN], g_ys[NN];
__device__ __align__(16) float g_su[NN], g_sv[NN];
__device__ float g_part[NBLK];
__device__ __align__(16) unsigned g_flags[NBLK];

extern __shared__ float dsm[];

// ---------------- flag barrier: parallel arrivals, acquire-poll ------------
__device__ __forceinline__ void garrive(int b, unsigned gen) {
    __syncthreads();
    if (threadIdx.x == 0)
        asm volatile("st.release.gpu.global.u32 [%0], %1;"
                     :: "l"(&g_flags[b]), "r"(gen) : "memory");
}
__device__ __forceinline__ void gwait(unsigned gen) {
    if (threadIdx.x < 32) {
        const int l = threadIdx.x;
        unsigned v0, v1, v2, v3;
        bool ok;
        do {
            asm volatile("ld.acquire.gpu.global.u32 %0, [%1];"
                         : "=r"(v0) : "l"(&g_flags[l]) : "memory");
            asm volatile("ld.acquire.gpu.global.u32 %0, [%1];"
                         : "=r"(v1) : "l"(&g_flags[l + 32]) : "memory");
            asm volatile("ld.acquire.gpu.global.u32 %0, [%1];"
                         : "=r"(v2) : "l"(&g_flags[l + 64]) : "memory");
            asm volatile("ld.acquire.gpu.global.u32 %0, [%1];"
                         : "=r"(v3) : "l"(&g_flags[l + 96]) : "memory");
            ok = (v0 >= gen) && (v1 >= gen) && (v2 >= gen) && (v3 >= gen);
        } while (!__all_sync(~0u, ok));
    }
    __syncthreads();
}
__device__ __forceinline__ void gsync(int b, unsigned gen) {
    garrive(b, gen);
    gwait(gen);
}

// ---------------- init: norms, transposes, su, flag reset ------------------
__global__ __launch_bounds__(256) void k_init(const float* __restrict__ x,
                                              const float* __restrict__ y) {
    __shared__ float s[16 * 65];
    const int tid = threadIdx.x;
    const int b = blockIdx.x;
    const int w = tid >> 5, l = tid & 31;

    if (b == 0 && tid < NBLK) g_flags[tid] = 0;
#pragma unroll
    for (int rr = 0; rr < 2; rr++) {
        const int row = b * 16 + rr * 8 + w;
        float2 vx = *(const float2*)(x + (size_t)row * DD + 2 * l);
        float sx = vx.x * vx.x + vx.y * vx.y;
        float2 vy = *(const float2*)(y + (size_t)row * DD + 2 * l);
        float sy = vy.x * vy.x + vy.y * vy.y;
#pragma unroll
        for (int o = 16; o; o >>= 1) {
            sx += __shfl_xor_sync(~0u, sx, o);
            sy += __shfl_xor_sync(~0u, sy, o);
        }
        if (l == 0) { g_xs[row] = sx; g_ys[row] = sy; }
    }
    if (tid < 16) g_su[b * 16 + tid] = AB;
    for (int i = tid; i < 16 * 64; i += 256) {
        int r = i >> 6, k = i & 63;
        s[r * 65 + k] = x[(size_t)(b * 16 + r) * DD + k];
    }
    __syncthreads();
    for (int i = tid; i < 16 * 64; i += 256) {
        int k = i >> 4, c = i & 15;
        g_xT[(size_t)k * NN + b * 16 + c] = s[c * 65 + k];
    }
    __syncthreads();
    for (int i = tid; i < 16 * 64; i += 256) {
        int r = i >> 6, k = i & 63;
        s[r * 65 + k] = y[(size_t)(b * 16 + r) * DD + k];
    }
    __syncthreads();
    for (int i = tid; i < 16 * 64; i += 256) {
        int k = i >> 4, c = i & 15;
        g_yT[(size_t)k * NN + b * 16 + c] = s[c * 65 + k];
    }
}

// ---------------- shared matvec pass ---------------------------------------
// out[base+t] = AB / (sum_c Eb[base+t][c] * in[c] * INV_SCALE + EPSF)
// block owns 32 rows of Eb; warp w: 4 rows ((w&7)*4), col chunk (w>>3)*1024.
__device__ __forceinline__ void mv_pass(const uint4* __restrict__ Eb,
                                        const float* __restrict__ gin,
                                        float* __restrict__ gout,
                                        int b, int tid, int w, int l) {
    float* svec = dsm;                 // [4096]
    float* red = dsm + 4096;           // [32][4]
    {
        float4 v = __ldcg((const float4*)gin + tid);
        *(float4*)&svec[tid * 4] = v;
    }
    __syncthreads();
    const int rq = (w & 7) * 4;
    const int qc = (w >> 3) * 1024;
    const int row0 = b * 32 + rq;
    const uint4* ebase = Eb + (size_t)row0 * (NN / 8) + (qc >> 3) + l;
    float acc[4] = {};
#pragma unroll
    for (int s = 0; s < 4; s++) {
        const int cb = qc + s * 256 + l * 8;
        float4 v0 = *(const float4*)&svec[cb];
        float4 v1 = *(const float4*)&svec[cb + 4];
        const uint4* ep = ebase + s * 32;
#pragma unroll
        for (int r = 0; r < 4; r++) {
            uint4 ev = ep[r * (NN / 8)];
            const __half2* eh = (const __half2*)&ev;
            float2 e0 = __half22float2(eh[0]);
            float2 e1 = __half22float2(eh[1]);
            float2 e2 = __half22float2(eh[2]);
            float2 e3 = __half22float2(eh[3]);
            acc[r] += e0.x * v0.x + e0.y * v0.y + e1.x * v0.z + e1.y * v0.w
                    + e2.x * v1.x + e2.y * v1.y + e3.x * v1.z + e3.y * v1.w;
        }
    }
#pragma unroll
    for (int r = 0; r < 4; r++) {
        float v = acc[r];
#pragma unroll
        for (int o = 16; o; o >>= 1) v += __shfl_xor_sync(~0u, v, o);
        if (l == 0) red[(rq + r) * 4 + (w >> 3)] = v;
    }
    __syncthreads();
    if (tid < 32) {
        float4 r4 = *(const float4*)&red[tid * 4];
        float s = r4.x + r4.y + r4.z + r4.w;
        gout[b * 32 + tid] = AB / (s * INV_SCALE + EPSF);
    }
}

// ---------------- persistent: build E/E^T + 50 iterations + loss -----------
__global__ __launch_bounds__(NTHR, 1) void k_persist(float* __restrict__ out) {
    const int tid = threadIdx.x;
    const int b = blockIdx.x;
    const int w = tid >> 5, l = tid & 31;
    unsigned gen = 0;

    // ============ phase 1: build E + E^T (1024 tiles of 128x128) ===========
    {
        float* Xs = dsm;              // [64][128]
        float* Ys = dsm + 64 * 128;   // [64][128]
        const int tx = tid & 31, ty = tid >> 5;
        __half* Eh = (__half*)g_E4;
        __half* ETh = (__half*)g_ET4;
        for (int t = 0; t < 8; t++) {
            const int id = b + t * NBLK;
            const int i0 = (id >> 5) * 128, j0 = (id & 31) * 128;
            {
                const int k = tid >> 4, rb = (tid & 15) * 8;
                const float4* px = (const float4*)(g_xT + (size_t)k * NN + i0 + rb);
                const float4* py = (const float4*)(g_yT + (size_t)k * NN + j0 + rb);
                *(float4*)&Xs[k * 128 + rb]     = __ldcg(px);
                *(float4*)&Xs[k * 128 + rb + 4] = __ldcg(px + 1);
                *(float4*)&Ys[k * 128 + rb]     = __ldcg(py);
                *(float4*)&Ys[k * 128 + rb + 4] = __ldcg(py + 1);
            }
            __syncthreads();
            float acc[4][4] = {};
#pragma unroll 8
            for (int k = 0; k < 64; k++) {
                float4 a4 = *(const float4*)&Xs[k * 128 + ty * 4];
                float4 b4 = *(const float4*)&Ys[k * 128 + tx * 4];
                float ar[4] = {a4.x, a4.y, a4.z, a4.w};
                float br[4] = {b4.x, b4.y, b4.z, b4.w};
#pragma unroll
                for (int r = 0; r < 4; r++)
#pragma unroll
                    for (int c = 0; c < 4; c++) acc[r][c] += ar[r] * br[c];
            }
            float xr[4], yc[4];
#pragma unroll
            for (int r = 0; r < 4; r++) xr[r] = __ldcg(&g_xs[i0 + ty * 4 + r]);
            {
                float4 y4 = __ldcg((const float4*)&g_ys[j0 + tx * 4]);
                yc[0] = y4.x; yc[1] = y4.y; yc[2] = y4.z; yc[3] = y4.w;
            }
            __half hv[4][4];
#pragma unroll
            for (int r = 0; r < 4; r++)
#pragma unroll
                for (int c = 0; c < 4; c++)
                    hv[r][c] = __float2half_rn(
                        __expf((2.f * acc[r][c] - xr[r] - yc[c]) * INV_REG + LN_SCALE));
#pragma unroll
            for (int r = 0; r < 4; r++) {
                union { uint2 u; __half2 h[2]; } pk;
                pk.h[0] = __halves2half2(hv[r][0], hv[r][1]);
                pk.h[1] = __halves2half2(hv[r][2], hv[r][3]);
                *(uint2*)(Eh + (size_t)(i0 + ty * 4 + r) * NN + j0 + tx * 4) = pk.u;
            }
#pragma unroll
            for (int c = 0; c < 4; c++) {
                union { uint2 u; __half2 h[2]; } pk;
                pk.h[0] = __halves2half2(hv[0][c], hv[1][c]);
                pk.h[1] = __halves2half2(hv[2][c], hv[3][c]);
                *(uint2*)(ETh + (size_t)(j0 + tx * 4 + c) * NN + i0 + ty * 4) = pk.u;
            }
            __syncthreads();
        }
    }
    gsync(b, ++gen);

    // ============ phase 2: 50 Sinkhorn iterations ==========================
    for (int it = 0; it < NITER; it++) {
        mv_pass(g_ET4, g_su, g_sv, b, tid, w, l);      // col pass (over E^T)
        gsync(b, ++gen);
        mv_pass(g_E4, g_sv, g_su, b, tid, w, l);       // row pass
        if (it < NITER - 1) gsync(b, ++gen);
    }

    // ============ phase 2b: loss — reuses ssv staged by last row pass ======
    {
        float* svec = dsm;             // still holds sv
        float* red = dsm + 4096;
        __syncthreads();               // row pass fully done (incl. g_su writes)
        const int rq = (w & 7) * 4;
        const int qc = (w >> 3) * 1024;
        const int row0 = b * 32 + rq;
        const uint4* ebase = g_E4 + (size_t)row0 * (NN / 8) + (qc >> 3) + l;
        float acc[4] = {};
#pragma unroll 1
        for (int s = 0; s < 4; s++) {
            const int cb = qc + s * 256 + l * 8;
            float4 v0 = *(const float4*)&svec[cb];
            float4 v1 = *(const float4*)&svec[cb + 4];
            const uint4* ep = ebase + s * 32;
#pragma unroll
            for (int r = 0; r < 4; r++) {
                uint4 ev = ep[r * (NN / 8)];
                const __half2* eh = (const __half2*)&ev;
                float2 ef[4];
                ef[0] = __half22float2(eh[0]);
                ef[1] = __half22float2(eh[1]);
                ef[2] = __half22float2(eh[2]);
                ef[3] = __half22float2(eh[3]);
                float vv[8] = {v0.x, v0.y, v0.z, v0.w, v1.x, v1.y, v1.z, v1.w};
#pragma unroll
                for (int q = 0; q < 8; q++) {
                    float e = ((float*)ef)[q];
                    float tq = (e > 0.f) ? e * (LN_SCALE - __logf(e)) : 0.f;
                    acc[r] += tq * vv[q];
                }
            }
        }
#pragma unroll
        for (int r = 0; r < 4; r++) {
            float v = acc[r];
#pragma unroll
            for (int o = 16; o; o >>= 1) v += __shfl_xor_sync(~0u, v, o);
            if (l == 0) red[(rq + r) * 4 + (w >> 3)] = v;
        }
        __syncthreads();
        if (tid < 32) {
            float4 r4 = *(const float4*)&red[tid * 4];
            float s = (r4.x + r4.y + r4.z + r4.w) * __ldcg(&g_su[b * 32 + tid]);
#pragma unroll
            for (int o = 16; o; o >>= 1) s += __shfl_xor_sync(~0u, s, o);
            if (tid == 0) g_part[b] = REGI * INV_SCALE * s;
        }
    }

    // ============ phase 3: final reduction (block 0 only polls) ============
    garrive(b, ++gen);
    if (b != 0) return;
    gwait(gen);
    if (tid < NBLK) {
        float v = __ldcg(&g_part[tid]);
#pragma unroll
        for (int o = 16; o; o >>= 1) v += __shfl_xor_sync(~0u, v, o);
        float* fs = dsm;
        if ((tid & 31) == 0) fs[tid >> 5] = v;
        __syncthreads();
        if (tid == 0) out[0] = fs[0] + fs[1] + fs[2] + fs[3];
    }
}

// ---------------------------------------------------------------------------
extern "C" void kernel_launch(void* const* d_in, const int* in_sizes, int n_in,
                              void* d_out, int out_size) {
    const float* x = (const float*)d_in[0];
    const float* y = (const float*)d_in[1];
    float* out = (float*)d_out;

    cudaFuncSetAttribute(k_persist, cudaFuncAttributeMaxDynamicSharedMemorySize,
                         DSM_BYTES);
    k_init<<<256, 256>>>(x, y);
    k_persist<<<NBLK, NTHR, DSM_BYTES>>>(out);
}

// round 8
// speedup vs baseline: 1.2236x; 1.2236x over previous
#include <cuda_runtime.h>
#include <cuda_fp16.h>
#include <cstdint>

#define NN 4096
#define DD 64
#define NITER 50
#define REGI 10.0f
#define INV_REG 0.1f
#define EPSF 1e-16f
#define AB (1.0f / 4096.0f)
#define INV_SCALE (1.0f / 262144.0f)   // 2^-18
#define LN_SCALE 12.476649250079f      // 18*ln2
#define NWORK 512
#define NTHR 256
#define DSM_BYTES 34816

// ---------------- persistent device state (no cudaMalloc allowed) ----------
__device__ uint4 g_E4[(size_t)NN * NN / 8];    // E*2^18 fp16 row-major, 32 MiB
__device__ uint4 g_ET4[(size_t)NN * NN / 8];   // transpose, 32 MiB
__device__ __align__(16) float g_xs[NN], g_ys[NN];
__device__ __align__(16) float g_su[NN], g_sv[NN];
__device__ float g_part[NWORK];
__device__ unsigned g_flags[NWORK];
__device__ unsigned g_go[128];     // 4 used, stride 32 (separate 128B lines)

extern __shared__ float dsm[];

// ---------------- worker-side barrier ops ----------------------------------
__device__ __forceinline__ void warrive(int wb, unsigned gen) {
    __syncthreads();
    if (threadIdx.x == 0)
        asm volatile("st.release.gpu.global.u32 [%0], %1;"
                     :: "l"(&g_flags[wb]), "r"(gen) : "memory");
}
__device__ __forceinline__ void wwait(int wb, unsigned gen) {
    if (threadIdx.x == 0) {
        unsigned* goaddr = &g_go[(wb & 3) * 32];
        unsigned v;
        do {
            asm volatile("ld.relaxed.gpu.global.u32 %0, [%1];"
                         : "=r"(v) : "l"(goaddr) : "memory");
        } while (v < gen);
        asm volatile("ld.acquire.gpu.global.u32 %0, [%1];"
                     : "=r"(v) : "l"(goaddr) : "memory");
    }
    __syncthreads();
}

// ---------------- coordinator: poll 512 flags, publish go ------------------
__device__ __forceinline__ void coord_release(int tid, unsigned gen) {
    // tid < 32 assumed
    bool ok;
    do {
        ok = true;
#pragma unroll
        for (int q = 0; q < 16; q++) {
            unsigned v;
            asm volatile("ld.relaxed.gpu.global.u32 %0, [%1];"
                         : "=r"(v) : "l"(&g_flags[tid * 16 + q]) : "memory");
            ok &= (v >= gen);
        }
    } while (!__all_sync(~0u, ok));
    asm volatile("fence.acq_rel.gpu;" ::: "memory");
    if (tid < 4)
        asm volatile("st.release.gpu.global.u32 [%0], %1;"
                     :: "l"(&g_go[tid * 32]), "r"(gen) : "memory");
}

// ---------------- init: norms, su, flag/go reset ---------------------------
__global__ __launch_bounds__(256) void k_init(const float* __restrict__ x,
                                              const float* __restrict__ y) {
    const int tid = threadIdx.x;
    const int b = blockIdx.x;
    const int w = tid >> 5, l = tid & 31;

    if (b < 2) g_flags[b * 256 + tid] = 0;
    if (b == 2 && tid < 128) g_go[tid] = 0;
#pragma unroll
    for (int rr = 0; rr < 2; rr++) {
        const int row = b * 16 + rr * 8 + w;
        float2 vx = *(const float2*)(x + (size_t)row * DD + 2 * l);
        float sx = vx.x * vx.x + vx.y * vx.y;
        float2 vy = *(const float2*)(y + (size_t)row * DD + 2 * l);
        float sy = vy.x * vy.x + vy.y * vy.y;
#pragma unroll
        for (int o = 16; o; o >>= 1) {
            sx += __shfl_xor_sync(~0u, sx, o);
            sy += __shfl_xor_sync(~0u, sy, o);
        }
        if (l == 0) { g_xs[row] = sx; g_ys[row] = sy; }
    }
    if (tid < 16) g_su[b * 16 + tid] = AB;
}

// ---------------- matvec pass: CTA owns 8 rows of Eb -----------------------
// warp w: row-quad (w&1)*4, col chunk (w>>1)*1024.
__device__ __forceinline__ void mv_pass(const uint4* __restrict__ Eb,
                                        const float* __restrict__ gin,
                                        float* __restrict__ gout,
                                        int wb, int tid, int w, int l) {
    float* svec = dsm;                  // [4096]
    float* red = dsm + 4096;            // [8][4]
#pragma unroll
    for (int r = 0; r < 4; r++) {
        int idx = tid + r * NTHR;
        *(float4*)&svec[idx * 4] = __ldcg((const float4*)gin + idx);
    }
    __syncthreads();
    const int rq = (w & 1) * 4;
    const int qc = (w >> 1) * 1024;
    const int row0 = wb * 8 + rq;
    const uint4* ebase = Eb + (size_t)row0 * (NN / 8) + (qc >> 3) + l;
    float acc[4] = {};
#pragma unroll
    for (int s = 0; s < 4; s++) {
        const int cb = qc + s * 256 + l * 8;
        float4 v0 = *(const float4*)&svec[cb];
        float4 v1 = *(const float4*)&svec[cb + 4];
        const uint4* ep = ebase + s * 32;
#pragma unroll
        for (int r = 0; r < 4; r++) {
            uint4 ev = ep[(size_t)r * (NN / 8)];
            const __half2* eh = (const __half2*)&ev;
            float2 e0 = __half22float2(eh[0]);
            float2 e1 = __half22float2(eh[1]);
            float2 e2 = __half22float2(eh[2]);
            float2 e3 = __half22float2(eh[3]);
            acc[r] += e0.x * v0.x + e0.y * v0.y + e1.x * v0.z + e1.y * v0.w
                    + e2.x * v1.x + e2.y * v1.y + e3.x * v1.z + e3.y * v1.w;
        }
    }
#pragma unroll
    for (int r = 0; r < 4; r++) {
        float v = acc[r];
#pragma unroll
        for (int o = 16; o; o >>= 1) v += __shfl_xor_sync(~0u, v, o);
        if (l == 0) red[(rq + r) * 4 + (w >> 1)] = v;
    }
    __syncthreads();
    if (tid < 8) {
        float4 r4 = *(const float4*)&red[tid * 4];
        float s = r4.x + r4.y + r4.z + r4.w;
        gout[wb * 8 + tid] = AB / (s * INV_SCALE + EPSF);
    }
}

// ---------------- persistent kernel ----------------------------------------
__global__ __launch_bounds__(NTHR, 4) void k_persist(const float* __restrict__ x,
                                                     const float* __restrict__ y,
                                                     float* __restrict__ out) {
    const int tid = threadIdx.x;
    const int b = blockIdx.x;
    const int w = tid >> 5, l = tid & 31;

    // ============ coordinator CTA ==========================================
    if (b == 0) {
        if (tid < 32) {
            for (unsigned gen = 1; gen <= 100; gen++) coord_release(tid, gen);
            // final arrivals (gen 101): poll + fence, no go needed
            bool ok;
            do {
                ok = true;
#pragma unroll
                for (int q = 0; q < 16; q++) {
                    unsigned v;
                    asm volatile("ld.relaxed.gpu.global.u32 %0, [%1];"
                                 : "=r"(v) : "l"(&g_flags[tid * 16 + q]) : "memory");
                    ok &= (v >= 101u);
                }
            } while (!__all_sync(~0u, ok));
            asm volatile("fence.acq_rel.gpu;" ::: "memory");
        }
        __syncthreads();
        float v = __ldcg(&g_part[tid]) + __ldcg(&g_part[tid + 256]);
#pragma unroll
        for (int o = 16; o; o >>= 1) v += __shfl_xor_sync(~0u, v, o);
        if (l == 0) dsm[w] = v;
        __syncthreads();
        if (tid == 0) {
            float s = 0.f;
#pragma unroll
            for (int q = 0; q < 8; q++) s += dsm[q];
            out[0] = s;
        }
        return;
    }

    const int wb = b - 1;   // 0..511

    // ============ phase 1: build E + E^T (4096 tiles of 64x64, 8 each) =====
    {
        float* Xs = dsm;             // [64][68] transposed
        float* Ys = dsm + 64 * 68;   // [64][68]
        const int tx = tid & 15, ty = tid >> 4;
        __half* Eh = (__half*)g_E4;
        __half* ETh = (__half*)g_ET4;
        for (int t = 0; t < 8; t++) {
            const int id = wb + t * NWORK;
            const int i0 = (id >> 6) * 64, j0 = (id & 63) * 64;
            for (int i = tid; i < 64 * 64; i += NTHR) {
                int r = i >> 6, k = i & 63;
                Xs[k * 68 + r] = x[(size_t)(i0 + r) * DD + k];
                Ys[k * 68 + r] = y[(size_t)(j0 + r) * DD + k];
            }
            __syncthreads();
            float acc[4][4] = {};
#pragma unroll 8
            for (int k = 0; k < 64; k++) {
                float4 a4 = *(const float4*)&Xs[k * 68 + ty * 4];
                float4 b4 = *(const float4*)&Ys[k * 68 + tx * 4];
                float ar[4] = {a4.x, a4.y, a4.z, a4.w};
                float br[4] = {b4.x, b4.y, b4.z, b4.w};
#pragma unroll
                for (int r = 0; r < 4; r++)
#pragma unroll
                    for (int c = 0; c < 4; c++) acc[r][c] += ar[r] * br[c];
            }
            float xr[4], yc[4];
#pragma unroll
            for (int r = 0; r < 4; r++) xr[r] = __ldcg(&g_xs[i0 + ty * 4 + r]);
            {
                float4 y4 = __ldcg((const float4*)&g_ys[j0 + tx * 4]);
                yc[0] = y4.x; yc[1] = y4.y; yc[2] = y4.z; yc[3] = y4.w;
            }
            __half hv[4][4];
#pragma unroll
            for (int r = 0; r < 4; r++)
#pragma unroll
                for (int c = 0; c < 4; c++)
                    hv[r][c] = __float2half_rn(
                        __expf((2.f * acc[r][c] - xr[r] - yc[c]) * INV_REG + LN_SCALE));
#pragma unroll
            for (int r = 0; r < 4; r++) {
                union { uint2 u; __half2 h[2]; } pk;
                pk.h[0] = __halves2half2(hv[r][0], hv[r][1]);
                pk.h[1] = __halves2half2(hv[r][2], hv[r][3]);
                *(uint2*)(Eh + (size_t)(i0 + ty * 4 + r) * NN + j0 + tx * 4) = pk.u;
            }
#pragma unroll
            for (int c = 0; c < 4; c++) {
                union { uint2 u; __half2 h[2]; } pk;
                pk.h[0] = __halves2half2(hv[0][c], hv[1][c]);
                pk.h[1] = __halves2half2(hv[2][c], hv[3][c]);
                *(uint2*)(ETh + (size_t)(j0 + tx * 4 + c) * NN + i0 + ty * 4) = pk.u;
            }
            __syncthreads();
        }
    }
    warrive(wb, 1);
    wwait(wb, 1);

    // ============ phase 2: 50 Sinkhorn iterations ==========================
    for (int it = 0; it < NITER; it++) {
        mv_pass(g_ET4, g_su, g_sv, wb, tid, w, l);     // col pass (over E^T)
        warrive(wb, 2 + 2 * it);
        wwait(wb, 2 + 2 * it);
        mv_pass(g_E4, g_sv, g_su, wb, tid, w, l);      // row pass
        if (it < NITER - 1) {
            warrive(wb, 3 + 2 * it);
            wwait(wb, 3 + 2 * it);
        }
    }

    // ============ phase 2b: loss — svec still holds sv (block-local) =======
    {
        float* svec = dsm;
        float* red = dsm + 4096;
        __syncthreads();               // row-pass red consumers done
        const int rq = (w & 1) * 4;
        const int qc = (w >> 1) * 1024;
        const int row0 = wb * 8 + rq;
        const uint4* ebase = g_E4 + (size_t)row0 * (NN / 8) + (qc >> 3) + l;
        float acc[4] = {};
#pragma unroll 1
        for (int s = 0; s < 4; s++) {
            const int cb = qc + s * 256 + l * 8;
            float4 v0 = *(const float4*)&svec[cb];
            float4 v1 = *(const float4*)&svec[cb + 4];
            const uint4* ep = ebase + s * 32;
#pragma unroll
            for (int r = 0; r < 4; r++) {
                uint4 ev = ep[(size_t)r * (NN / 8)];
                const __half2* eh = (const __half2*)&ev;
                float2 ef[4];
                ef[0] = __half22float2(eh[0]);
                ef[1] = __half22float2(eh[1]);
                ef[2] = __half22float2(eh[2]);
                ef[3] = __half22float2(eh[3]);
                float vv[8] = {v0.x, v0.y, v0.z, v0.w, v1.x, v1.y, v1.z, v1.w};
#pragma unroll
                for (int q = 0; q < 8; q++) {
                    float e = ((float*)ef)[q];
                    float tq = (e > 0.f) ? e * (LN_SCALE - __logf(e)) : 0.f;
                    acc[r] += tq * vv[q];
                }
            }
        }
#pragma unroll
        for (int r = 0; r < 4; r++) {
            float v = acc[r];
#pragma unroll
            for (int o = 16; o; o >>= 1) v += __shfl_xor_sync(~0u, v, o);
            if (l == 0) red[(rq + r) * 4 + (w >> 1)] = v;
        }
        __syncthreads();
        if (tid < 8) {
            float4 r4 = *(const float4*)&red[tid * 4];
            float s = (r4.x + r4.y + r4.z + r4.w) * __ldcg(&g_su[wb * 8 + tid]);
            dsm[4096 + 32 + tid] = REGI * INV_SCALE * s;
        }
        __syncthreads();
        if (tid == 0) {
            float s = 0.f;
#pragma unroll
            for (int q = 0; q < 8; q++) s += dsm[4096 + 32 + q];
            g_part[wb] = s;
        }
    }
    warrive(wb, 101);
}

// ---------------------------------------------------------------------------
extern "C" void kernel_launch(void* const* d_in, const int* in_sizes, int n_in,
                              void* d_out, int out_size) {
    const float* x = (const float*)d_in[0];
    const float* y = (const float*)d_in[1];
    float* out = (float*)d_out;

    cudaFuncSetAttribute(k_persist, cudaFuncAttributeMaxDynamicSharedMemorySize,
                         DSM_BYTES);
    k_init<<<256, 256>>>(x, y);
    k_persist<<<NWORK + 1, NTHR, DSM_BYTES>>>(x, y, out);
}